// round 5
// baseline (speedup 1.0000x reference)
#include <cuda_runtime.h>
#include <cstdint>

// ---------------------------------------------------------------------------
// QINCo inference step encoder, factorized (see R0-R3 notes):
//   u1 = A1g[k] + A1t[bf];            r1 = relu(u1)
//   u2 = A2g[k] + A2t[bf] + r1@M12;   r2 = relu(u2)     (M12 = W2[0]@W1[1])
//   cw = Og[k] + Ot[bf] + r1@M1o + r2@M2o
//   dist = || Og[k] + (Ot[bf]-x_b) + corr ||^2 ; argmin per b; recompute winner.
// R4: inner GEMMs use packed fma.rn.f32x2 (FFMA2) -> 2x fp32 pipe.
// Output: 33152 f32 = [xhat_next 32768][codes 384 as float values]; codes in = int32.
// ---------------------------------------------------------------------------

#define Bb   128
#define Ff   8
#define Kk   256
#define Dd   256
#define Hh   256
#define HFF  512

typedef unsigned long long ull;

__device__ __forceinline__ void ffma2(ull &acc, ull a, ull b) {
    asm("fma.rn.f32x2 %0, %1, %2, %0;" : "+l"(acc) : "l"(a), "l"(b));
}
__device__ __forceinline__ ull dup2(float v) {
    ull r; asm("mov.b64 %0, {%1, %1};" : "=l"(r) : "f"(v)); return r;
}
__device__ __forceinline__ float2 ull2f2(ull v) {
    float2 f; asm("mov.b64 {%0, %1}, %2;" : "=f"(f.x), "=f"(f.y) : "l"(v)); return f;
}

// -------------------- scratch (device globals; no allocs) -------------------
__device__ float g_h0 [Kk*Hh];
__device__ float g_g  [Kk*Hh];
__device__ float g_t  [Bb*Ff*Hh];
__device__ float g_A1g[Kk*HFF];
__device__ float g_A2g[Kk*HFF];
__device__ float g_A1t[Bb*Ff*HFF];
__device__ float g_A2t[Bb*Ff*HFF];
__device__ float g_Og [Kk*Dd];
__device__ float g_Ot [Bb*Ff*Dd];
__device__ float g_M12[HFF*HFF];
__device__ float g_M1o[HFF*Dd];
__device__ float g_M2o[HFF*Dd];
__device__ float g_bu2[HFF];
__device__ float g_bo [Dd];
__device__ float g_dists[Bb*Ff*Kk];
__device__ int   g_idx[Bb];

// -------------------- generic small SGEMM: C = A@B (+bias)(+Add) ------------
__global__ __launch_bounds__(256) void sgemm64(
    const float* __restrict__ A, const float* __restrict__ B, float* __restrict__ C,
    int M, int N, int K, const float* __restrict__ bias, const float* __restrict__ add)
{
    __shared__ float As[16][65];
    __shared__ float Bs[16][64];
    const int m0 = blockIdx.y * 64;
    const int n0 = blockIdx.x * 64;
    const int tid = threadIdx.x;
    const int tx = tid & 15, ty = tid >> 4;
    float acc[4][4] = {};

    for (int k0 = 0; k0 < K; k0 += 16) {
        {
            int ra = tid >> 2, ca = (tid & 3) * 4;
            float4 av = *(const float4*)(A + (size_t)(m0 + ra) * K + k0 + ca);
            As[ca+0][ra] = av.x; As[ca+1][ra] = av.y;
            As[ca+2][ra] = av.z; As[ca+3][ra] = av.w;
        }
        {
            int rb = tid >> 4, cb = (tid & 15) * 4;
            *(float4*)&Bs[rb][cb] = *(const float4*)(B + (size_t)(k0 + rb) * N + n0 + cb);
        }
        __syncthreads();
        #pragma unroll
        for (int kk = 0; kk < 16; kk++) {
            float a0 = As[kk][ty*4+0], a1 = As[kk][ty*4+1];
            float a2 = As[kk][ty*4+2], a3 = As[kk][ty*4+3];
            float4 bv = *(float4*)&Bs[kk][tx*4];
            acc[0][0] += a0*bv.x; acc[0][1] += a0*bv.y; acc[0][2] += a0*bv.z; acc[0][3] += a0*bv.w;
            acc[1][0] += a1*bv.x; acc[1][1] += a1*bv.y; acc[1][2] += a1*bv.z; acc[1][3] += a1*bv.w;
            acc[2][0] += a2*bv.x; acc[2][1] += a2*bv.y; acc[2][2] += a2*bv.z; acc[2][3] += a2*bv.w;
            acc[3][0] += a3*bv.x; acc[3][1] += a3*bv.y; acc[3][2] += a3*bv.z; acc[3][3] += a3*bv.w;
        }
        __syncthreads();
    }
    #pragma unroll
    for (int i = 0; i < 4; i++) {
        int m = m0 + ty*4 + i;
        #pragma unroll
        for (int j = 0; j < 4; j++) {
            int n = n0 + tx*4 + j;
            float v = acc[i][j];
            if (bias) v += bias[n];
            if (add)  v += add[(size_t)m * N + n];
            C[(size_t)m * N + n] = v;
        }
    }
}

// out[j] = base[j] + sum_i (v1[i] + v2?[i]) * Mat[i*N + j]
__global__ void vecmat_bias(float* __restrict__ out, const float* __restrict__ base,
                            const float* __restrict__ v1, const float* __restrict__ v2,
                            const float* __restrict__ Mat, int K, int N)
{
    int j = blockIdx.x * blockDim.x + threadIdx.x;
    if (j >= N) return;
    float s = base[j];
    for (int i = 0; i < K; i++) {
        float v = v1[i];
        if (v2) v += v2[i];
        s += v * Mat[(size_t)i * N + j];
    }
    out[j] = s;
}

// -------------------- packed GEMM tile ---------------------------------------
// A in smem k-major: AsmT[k*34 + m] (m = 0..31, pad 34 -> 2-way write conflicts only).
// B streamed from global via Bt[32][128]. Output tile 32(M) x 128(N); thread
// (tm 0..7, tn 0..31) owns m = tm*4..+3, n = tn*4..+3 as 2 packed pairs.
// acc[2*i + j] = f32x2 pair for (m = tm*4+i, n = tn*4+2j .. +1).
__device__ __forceinline__ void gemm_tile_p(
    ull* __restrict__ acc, const float* __restrict__ AsmT,
    const float* __restrict__ Bg, int ldb, int kTot,
    float (*Bt)[128], int tid, int tm, int tn)
{
    const int rw = tid >> 5;
    const int c4 = (tid & 31) * 4;
    for (int kc = 0; kc < kTot; kc += 32) {
        __syncthreads();   // protect Bt from previous consumers
        #pragma unroll
        for (int i = 0; i < 4; i++) {
            int r = rw + i * 8;
            *(float4*)&Bt[r][c4] = *(const float4*)(Bg + (size_t)(kc + r) * ldb + c4);
        }
        __syncthreads();
        const float* arow = AsmT + kc*34 + tm*4;
        #pragma unroll 8
        for (int kk = 0; kk < 32; kk++) {
            float2 a01 = *(const float2*)(arow);         // LDS.64 broadcast
            float2 a23 = *(const float2*)(arow + 2);
            ulonglong2 bv = *(const ulonglong2*)&Bt[kk][tn*4];  // 2 natural n-pairs
            ull p;
            p = dup2(a01.x); ffma2(acc[0], p, bv.x); ffma2(acc[1], p, bv.y);
            p = dup2(a01.y); ffma2(acc[2], p, bv.x); ffma2(acc[3], p, bv.y);
            p = dup2(a23.x); ffma2(acc[4], p, bv.x); ffma2(acc[5], p, bv.y);
            p = dup2(a23.y); ffma2(acc[6], p, bv.x); ffma2(acc[7], p, bv.y);
            arow += 34;
        }
    }
}

// smem: a1t 512 | a2t 512 | otx 256 | R1T 512*34 | Bt 32*128 | R2T 128*34
#define OFF_A1T  0
#define OFF_A2T  512
#define OFF_OTX  1024
#define OFF_R1T  1280
#define OFF_BT   (1280 + 512*34)
#define OFF_R2T  (OFF_BT + 32*128)
#define DIST_SMEM_FLOATS (OFF_R2T + 128*34)   // 27136 floats = 108544 B

__global__ __launch_bounds__(256, 2) void dist_kernel(const float* __restrict__ x)
{
    extern __shared__ float sm[];
    float* a1t = sm + OFF_A1T;
    float* a2t = sm + OFF_A2T;
    float* otx = sm + OFF_OTX;
    float* R1T = sm + OFF_R1T;                   // [512][34] k-major
    float (*Bt)[128] = (float(*)[128])(sm + OFF_BT);
    float* R2T = sm + OFF_R2T;                   // [128][34] k-major (per panel)

    const int bf = blockIdx.x;
    const int b  = bf >> 3;
    const int f  = bf & 7;
    const int tid = threadIdx.x;
    const int tm = tid >> 5, tn = tid & 31;

    for (int i = tid; i < 512; i += 256) {
        a1t[i] = g_A1t[(size_t)bf*512 + i];
        a2t[i] = g_A2t[(size_t)bf*512 + i];
    }
    if (tid < 256) otx[tid] = g_Ot[(size_t)bf*256 + tid] - x[(size_t)b*256 + tid];

    #pragma unroll 1
    for (int k0 = 0; k0 < 256; k0 += 32) {
        __syncthreads();   // protect R1T from previous iteration's readers
        // R1T[c][r] = relu(A1g[k0+r][c] + a1t[c]);  c fast -> coalesced LDG,
        // STS banks (2c+r)%32 -> 2-way only.
        for (int i = tid; i < 32*512; i += 256) {
            int r = i >> 9, c = i & 511;
            R1T[c*34 + r] = fmaxf(g_A1g[(size_t)(k0 + r)*512 + c] + a1t[c], 0.f);
        }
        // (gemm_tile_p's leading barrier orders R1T writes before reads)

        ull corr0[8] = {}, corr1[8] = {};
        gemm_tile_p(corr0, R1T, g_M1o,       256, 512, Bt, tid, tm, tn);
        gemm_tile_p(corr1, R1T, g_M1o + 128, 256, 512, Bt, tid, tm, tn);

        #pragma unroll 1
        for (int p = 0; p < 4; p++) {
            ull u2a[8] = {};
            gemm_tile_p(u2a, R1T, g_M12 + p*128, 512, 512, Bt, tid, tm, tn);
            __syncthreads();   // previous panel's R2T readers done
            #pragma unroll
            for (int i = 0; i < 4; i++) {
                int r = tm*4 + i;
                float4 gv = *(const float4*)(g_A2g + (size_t)(k0 + r)*512 + p*128 + tn*4);
                float4 tv = *(const float4*)(a2t + p*128 + tn*4);
                float2 ua = ull2f2(u2a[2*i]);
                float2 ub = ull2f2(u2a[2*i+1]);
                int cb = tn*4;
                R2T[(cb+0)*34 + r] = fmaxf(ua.x + gv.x + tv.x, 0.f);
                R2T[(cb+1)*34 + r] = fmaxf(ua.y + gv.y + tv.y, 0.f);
                R2T[(cb+2)*34 + r] = fmaxf(ub.x + gv.z + tv.z, 0.f);
                R2T[(cb+3)*34 + r] = fmaxf(ub.y + gv.w + tv.w, 0.f);
            }
            gemm_tile_p(corr0, R2T, g_M2o + (size_t)p*128*256,       256, 128, Bt, tid, tm, tn);
            gemm_tile_p(corr1, R2T, g_M2o + (size_t)p*128*256 + 128, 256, 128, Bt, tid, tm, tn);
        }

        // distances for the 32 rows of this tile
        float part[4] = {};
        #pragma unroll
        for (int i = 0; i < 4; i++) {
            int r = tm*4 + i;
            float4 og0 = *(const float4*)(g_Og + (size_t)(k0 + r)*256 + tn*4);
            float4 og1 = *(const float4*)(g_Og + (size_t)(k0 + r)*256 + 128 + tn*4);
            float4 ox0 = *(const float4*)(otx + tn*4);
            float4 ox1 = *(const float4*)(otx + 128 + tn*4);
            float2 c0a = ull2f2(corr0[2*i]);
            float2 c0b = ull2f2(corr0[2*i+1]);
            float2 c1a = ull2f2(corr1[2*i]);
            float2 c1b = ull2f2(corr1[2*i+1]);
            float v;
            v = og0.x + ox0.x + c0a.x; part[i] += v*v;
            v = og0.y + ox0.y + c0a.y; part[i] += v*v;
            v = og0.z + ox0.z + c0b.x; part[i] += v*v;
            v = og0.w + ox0.w + c0b.y; part[i] += v*v;
            v = og1.x + ox1.x + c1a.x; part[i] += v*v;
            v = og1.y + ox1.y + c1a.y; part[i] += v*v;
            v = og1.z + ox1.z + c1b.x; part[i] += v*v;
            v = og1.w + ox1.w + c1b.y; part[i] += v*v;
        }
        #pragma unroll
        for (int i = 0; i < 4; i++) {
            #pragma unroll
            for (int off = 16; off > 0; off >>= 1)
                part[i] += __shfl_xor_sync(0xffffffffu, part[i], off);
        }
        if (tn == 0) {
            #pragma unroll
            for (int i = 0; i < 4; i++)
                g_dists[(size_t)b*2048 + f*256 + k0 + tm*4 + i] = part[i];
        }
    }
}

// -------------------- argmin per b (first occurrence on ties) ---------------
__global__ __launch_bounds__(256) void argmin_kernel()
{
    __shared__ float sv[256];
    __shared__ int   si[256];
    int b = blockIdx.x, tid = threadIdx.x;
    float best = 3.4e38f; int bi = 1 << 30;
    for (int i = tid; i < 2048; i += 256) {
        float v = g_dists[(size_t)b*2048 + i];
        if (v < best || (v == best && i < bi)) { best = v; bi = i; }
    }
    sv[tid] = best; si[tid] = bi;
    __syncthreads();
    for (int s = 128; s > 0; s >>= 1) {
        if (tid < s) {
            if (sv[tid+s] < sv[tid] || (sv[tid+s] == sv[tid] && si[tid+s] < si[tid])) {
                sv[tid] = sv[tid+s]; si[tid] = si[tid+s];
            }
        }
        __syncthreads();
    }
    if (tid == 0) g_idx[b] = si[0];
}

// -------------------- winner recompute + output -----------------------------
__global__ __launch_bounds__(512) void final_kernel(float* __restrict__ out)
{
    __shared__ float r1[512], r2[512];
    __shared__ int sIdx;
    int b = blockIdx.x, tid = threadIdx.x;
    if (tid == 0) sIdx = g_idx[b];
    __syncthreads();
    int idx = sIdx;
    int f = idx >> 8, k = idx & 255;
    int bf = b*8 + f;

    r1[tid] = fmaxf(g_A1g[(size_t)k*512 + tid] + g_A1t[(size_t)bf*512 + tid], 0.f);
    __syncthreads();
    {
        float s = g_A2g[(size_t)k*512 + tid] + g_A2t[(size_t)bf*512 + tid];
        for (int i = 0; i < 512; i++) s += r1[i] * g_M12[(size_t)i*512 + tid];
        r2[tid] = fmaxf(s, 0.f);
    }
    __syncthreads();
    if (tid < 256) {
        float s = g_Og[(size_t)k*256 + tid] + g_Ot[(size_t)bf*256 + tid];
        for (int i = 0; i < 512; i++)
            s += r1[i] * g_M1o[(size_t)i*256 + tid] + r2[i] * g_M2o[(size_t)i*256 + tid];
        out[b*256 + tid] = s;
    }
}

// codes region: floats [32768:33152] = [codes_MBF (256 int32->float), idx (128->float)]
__global__ void codes_kernel(const int* __restrict__ codes, float* __restrict__ out)
{
    int t = threadIdx.x;
    float* oc = out + Bb * Dd;
    if (t < 256)      oc[t] = (float)codes[t];
    else if (t < 384) oc[t] = (float)g_idx[t - 256];
}

// -------------------- launch ------------------------------------------------
extern "C" void kernel_launch(void* const* d_in, const int* in_sizes, int n_in,
                              void* d_out, int out_size)
{
    const float* x        = (const float*)d_in[0];
    const float* xhat     = (const float*)d_in[1];
    const int*   codes    = (const int*)d_in[2];   // int32
    const float* codebook = (const float*)d_in[3];
    const float* W_in     = (const float*)d_in[4];
    const float* b_in     = (const float*)d_in[5];
    const float* W_cat    = (const float*)d_in[6];
    const float* b_cat    = (const float*)d_in[7];
    const float* W1       = (const float*)d_in[8];
    const float* b1       = (const float*)d_in[9];
    const float* W2       = (const float*)d_in[10];
    const float* b2       = (const float*)d_in[11];
    const float* W_out    = (const float*)d_in[12];
    const float* b_out    = (const float*)d_in[13];
    float* out = (float*)d_out;

    float *p_h0, *p_g, *p_t, *p_A1g, *p_A2g, *p_A1t, *p_A2t, *p_Og, *p_Ot;
    float *p_M12, *p_M1o, *p_M2o, *p_bu2, *p_bo;
    cudaGetSymbolAddress((void**)&p_h0,  g_h0);
    cudaGetSymbolAddress((void**)&p_g,   g_g);
    cudaGetSymbolAddress((void**)&p_t,   g_t);
    cudaGetSymbolAddress((void**)&p_A1g, g_A1g);
    cudaGetSymbolAddress((void**)&p_A2g, g_A2g);
    cudaGetSymbolAddress((void**)&p_A1t, g_A1t);
    cudaGetSymbolAddress((void**)&p_A2t, g_A2t);
    cudaGetSymbolAddress((void**)&p_Og,  g_Og);
    cudaGetSymbolAddress((void**)&p_Ot,  g_Ot);
    cudaGetSymbolAddress((void**)&p_M12, g_M12);
    cudaGetSymbolAddress((void**)&p_M1o, g_M1o);
    cudaGetSymbolAddress((void**)&p_M2o, g_M2o);
    cudaGetSymbolAddress((void**)&p_bu2, g_bu2);
    cudaGetSymbolAddress((void**)&p_bo,  g_bo);

    const float* W1_0 = W1;                const float* W1_1 = W1 + 256*512;
    const float* W2_0 = W2;                const float* W2_1 = W2 + 512*256;
    const float* Wc   = W_cat;             const float* Wx   = W_cat + 256*256;
    const float* b1_1 = b1 + 512;
    const float* b2_0 = b2;                const float* b2_1 = b2 + 256;

    // bias folds: bu2 = b1[1] + b2[0]@W1[1] ; bo = b_out + (b2[0]+b2[1])@W_out
    vecmat_bias<<<2, 256>>>(p_bu2, b1_1, b2_0, nullptr, W1_1, 256, 512);
    vecmat_bias<<<1, 256>>>(p_bo,  b_out, b2_0, b2_1,   W_out, 256, 256);

    // precompute GEMMs
    sgemm64<<<dim3(4, 4),  256>>>(codebook, W_in,  p_h0,  256, 256, 256, b_in,  nullptr);
    sgemm64<<<dim3(4, 4),  256>>>(p_h0,     Wc,    p_g,   256, 256, 256, nullptr, nullptr);
    sgemm64<<<dim3(4, 16), 256>>>(xhat,     Wx,    p_t,  1024, 256, 256, b_cat, nullptr);
    sgemm64<<<dim3(8, 4),  256>>>(p_g,      W1_0,  p_A1g, 256, 512, 256, nullptr, nullptr);
    sgemm64<<<dim3(8, 16), 256>>>(p_t,      W1_0,  p_A1t,1024, 512, 256, b1,    nullptr);
    sgemm64<<<dim3(8, 4),  256>>>(p_g,      W1_1,  p_A2g, 256, 512, 256, nullptr, nullptr);
    sgemm64<<<dim3(8, 16), 256>>>(p_t,      W1_1,  p_A2t,1024, 512, 256, p_bu2, nullptr);
    sgemm64<<<dim3(4, 4),  256>>>(p_g,      W_out, p_Og,  256, 256, 256, nullptr, codebook);
    sgemm64<<<dim3(4, 16), 256>>>(p_t,      W_out, p_Ot, 1024, 256, 256, p_bo,  xhat);
    sgemm64<<<dim3(8, 8),  256>>>(W2_0,     W1_1,  p_M12, 512, 512, 256, nullptr, nullptr);
    sgemm64<<<dim3(4, 8),  256>>>(W2_0,     W_out, p_M1o, 512, 256, 256, nullptr, nullptr);
    sgemm64<<<dim3(4, 8),  256>>>(W2_1,     W_out, p_M2o, 512, 256, 256, nullptr, nullptr);

    // main distance pass (FFMA2)
    const int smem_bytes = DIST_SMEM_FLOATS * (int)sizeof(float);  // 108544
    cudaFuncSetAttribute(dist_kernel, cudaFuncAttributeMaxDynamicSharedMemorySize, smem_bytes);
    dist_kernel<<<Bb * Ff, 256, smem_bytes>>>(x);

    argmin_kernel<<<Bb, 256>>>();
    final_kernel<<<Bb, 512>>>(out);
    codes_kernel<<<1, 384>>>(codes, out);
}

// round 6
// speedup vs baseline: 1.0005x; 1.0005x over previous
#include <cuda_runtime.h>
#include <cstdint>

// ---------------------------------------------------------------------------
// QINCo inference step encoder, factorized (see R0-R3 notes):
//   u1 = A1g[k] + A1t[bf];            r1 = relu(u1)
//   u2 = A2g[k] + A2t[bf] + r1@M12;   r2 = relu(u2)     (M12 = W2[0]@W1[1])
//   cw = Og[k] + Ot[bf] + r1@M1o + r2@M2o
//   dist = || Og[k] + (Ot[bf]-x_b) + corr ||^2 ; argmin per b; recompute winner.
// R4: inner GEMMs use packed fma.rn.f32x2 (FFMA2) -> 2x fp32 pipe.
// Output: 33152 f32 = [xhat_next 32768][codes 384 as float values]; codes in = int32.
// ---------------------------------------------------------------------------

#define Bb   128
#define Ff   8
#define Kk   256
#define Dd   256
#define Hh   256
#define HFF  512

typedef unsigned long long ull;

__device__ __forceinline__ void ffma2(ull &acc, ull a, ull b) {
    asm("fma.rn.f32x2 %0, %1, %2, %0;" : "+l"(acc) : "l"(a), "l"(b));
}
__device__ __forceinline__ ull dup2(float v) {
    ull r; asm("mov.b64 %0, {%1, %1};" : "=l"(r) : "f"(v)); return r;
}
__device__ __forceinline__ float2 ull2f2(ull v) {
    float2 f; asm("mov.b64 {%0, %1}, %2;" : "=f"(f.x), "=f"(f.y) : "l"(v)); return f;
}

// -------------------- scratch (device globals; no allocs) -------------------
__device__ float g_h0 [Kk*Hh];
__device__ float g_g  [Kk*Hh];
__device__ float g_t  [Bb*Ff*Hh];
__device__ float g_A1g[Kk*HFF];
__device__ float g_A2g[Kk*HFF];
__device__ float g_A1t[Bb*Ff*HFF];
__device__ float g_A2t[Bb*Ff*HFF];
__device__ float g_Og [Kk*Dd];
__device__ float g_Ot [Bb*Ff*Dd];
__device__ float g_M12[HFF*HFF];
__device__ float g_M1o[HFF*Dd];
__device__ float g_M2o[HFF*Dd];
__device__ float g_bu2[HFF];
__device__ float g_bo [Dd];
__device__ float g_dists[Bb*Ff*Kk];
__device__ int   g_idx[Bb];

// -------------------- generic small SGEMM: C = A@B (+bias)(+Add) ------------
__global__ __launch_bounds__(256) void sgemm64(
    const float* __restrict__ A, const float* __restrict__ B, float* __restrict__ C,
    int M, int N, int K, const float* __restrict__ bias, const float* __restrict__ add)
{
    __shared__ float As[16][65];
    __shared__ float Bs[16][64];
    const int m0 = blockIdx.y * 64;
    const int n0 = blockIdx.x * 64;
    const int tid = threadIdx.x;
    const int tx = tid & 15, ty = tid >> 4;
    float acc[4][4] = {};

    for (int k0 = 0; k0 < K; k0 += 16) {
        {
            int ra = tid >> 2, ca = (tid & 3) * 4;
            float4 av = *(const float4*)(A + (size_t)(m0 + ra) * K + k0 + ca);
            As[ca+0][ra] = av.x; As[ca+1][ra] = av.y;
            As[ca+2][ra] = av.z; As[ca+3][ra] = av.w;
        }
        {
            int rb = tid >> 4, cb = (tid & 15) * 4;
            *(float4*)&Bs[rb][cb] = *(const float4*)(B + (size_t)(k0 + rb) * N + n0 + cb);
        }
        __syncthreads();
        #pragma unroll
        for (int kk = 0; kk < 16; kk++) {
            float a0 = As[kk][ty*4+0], a1 = As[kk][ty*4+1];
            float a2 = As[kk][ty*4+2], a3 = As[kk][ty*4+3];
            float4 bv = *(float4*)&Bs[kk][tx*4];
            acc[0][0] += a0*bv.x; acc[0][1] += a0*bv.y; acc[0][2] += a0*bv.z; acc[0][3] += a0*bv.w;
            acc[1][0] += a1*bv.x; acc[1][1] += a1*bv.y; acc[1][2] += a1*bv.z; acc[1][3] += a1*bv.w;
            acc[2][0] += a2*bv.x; acc[2][1] += a2*bv.y; acc[2][2] += a2*bv.z; acc[2][3] += a2*bv.w;
            acc[3][0] += a3*bv.x; acc[3][1] += a3*bv.y; acc[3][2] += a3*bv.z; acc[3][3] += a3*bv.w;
        }
        __syncthreads();
    }
    #pragma unroll
    for (int i = 0; i < 4; i++) {
        int m = m0 + ty*4 + i;
        #pragma unroll
        for (int j = 0; j < 4; j++) {
            int n = n0 + tx*4 + j;
            float v = acc[i][j];
            if (bias) v += bias[n];
            if (add)  v += add[(size_t)m * N + n];
            C[(size_t)m * N + n] = v;
        }
    }
}

// out[j] = base[j] + sum_i (v1[i] + v2?[i]) * Mat[i*N + j]
__global__ void vecmat_bias(float* __restrict__ out, const float* __restrict__ base,
                            const float* __restrict__ v1, const float* __restrict__ v2,
                            const float* __restrict__ Mat, int K, int N)
{
    int j = blockIdx.x * blockDim.x + threadIdx.x;
    if (j >= N) return;
    float s = base[j];
    for (int i = 0; i < K; i++) {
        float v = v1[i];
        if (v2) v += v2[i];
        s += v * Mat[(size_t)i * N + j];
    }
    out[j] = s;
}

// -------------------- packed GEMM tile ---------------------------------------
// A in smem k-major: AsmT[k*34 + m] (m = 0..31, pad 34 -> 2-way write conflicts only).
// B streamed from global via Bt[32][128]. Output tile 32(M) x 128(N); thread
// (tm 0..7, tn 0..31) owns m = tm*4..+3, n = tn*4..+3 as 2 packed pairs.
// acc[2*i + j] = f32x2 pair for (m = tm*4+i, n = tn*4+2j .. +1).
__device__ __forceinline__ void gemm_tile_p(
    ull* __restrict__ acc, const float* __restrict__ AsmT,
    const float* __restrict__ Bg, int ldb, int kTot,
    float (*Bt)[128], int tid, int tm, int tn)
{
    const int rw = tid >> 5;
    const int c4 = (tid & 31) * 4;
    for (int kc = 0; kc < kTot; kc += 32) {
        __syncthreads();   // protect Bt from previous consumers
        #pragma unroll
        for (int i = 0; i < 4; i++) {
            int r = rw + i * 8;
            *(float4*)&Bt[r][c4] = *(const float4*)(Bg + (size_t)(kc + r) * ldb + c4);
        }
        __syncthreads();
        const float* arow = AsmT + kc*34 + tm*4;
        #pragma unroll 8
        for (int kk = 0; kk < 32; kk++) {
            float2 a01 = *(const float2*)(arow);         // LDS.64 broadcast
            float2 a23 = *(const float2*)(arow + 2);
            ulonglong2 bv = *(const ulonglong2*)&Bt[kk][tn*4];  // 2 natural n-pairs
            ull p;
            p = dup2(a01.x); ffma2(acc[0], p, bv.x); ffma2(acc[1], p, bv.y);
            p = dup2(a01.y); ffma2(acc[2], p, bv.x); ffma2(acc[3], p, bv.y);
            p = dup2(a23.x); ffma2(acc[4], p, bv.x); ffma2(acc[5], p, bv.y);
            p = dup2(a23.y); ffma2(acc[6], p, bv.x); ffma2(acc[7], p, bv.y);
            arow += 34;
        }
    }
}

// smem: a1t 512 | a2t 512 | otx 256 | R1T 512*34 | Bt 32*128 | R2T 128*34
#define OFF_A1T  0
#define OFF_A2T  512
#define OFF_OTX  1024
#define OFF_R1T  1280
#define OFF_BT   (1280 + 512*34)
#define OFF_R2T  (OFF_BT + 32*128)
#define DIST_SMEM_FLOATS (OFF_R2T + 128*34)   // 27136 floats = 108544 B

__global__ __launch_bounds__(256, 2) void dist_kernel(const float* __restrict__ x)
{
    extern __shared__ float sm[];
    float* a1t = sm + OFF_A1T;
    float* a2t = sm + OFF_A2T;
    float* otx = sm + OFF_OTX;
    float* R1T = sm + OFF_R1T;                   // [512][34] k-major
    float (*Bt)[128] = (float(*)[128])(sm + OFF_BT);
    float* R2T = sm + OFF_R2T;                   // [128][34] k-major (per panel)

    const int bf = blockIdx.x;
    const int b  = bf >> 3;
    const int f  = bf & 7;
    const int tid = threadIdx.x;
    const int tm = tid >> 5, tn = tid & 31;

    for (int i = tid; i < 512; i += 256) {
        a1t[i] = g_A1t[(size_t)bf*512 + i];
        a2t[i] = g_A2t[(size_t)bf*512 + i];
    }
    if (tid < 256) otx[tid] = g_Ot[(size_t)bf*256 + tid] - x[(size_t)b*256 + tid];

    #pragma unroll 1
    for (int k0 = 0; k0 < 256; k0 += 32) {
        __syncthreads();   // protect R1T from previous iteration's readers
        // R1T[c][r] = relu(A1g[k0+r][c] + a1t[c]);  c fast -> coalesced LDG,
        // STS banks (2c+r)%32 -> 2-way only.
        for (int i = tid; i < 32*512; i += 256) {
            int r = i >> 9, c = i & 511;
            R1T[c*34 + r] = fmaxf(g_A1g[(size_t)(k0 + r)*512 + c] + a1t[c], 0.f);
        }
        // (gemm_tile_p's leading barrier orders R1T writes before reads)

        ull corr0[8] = {}, corr1[8] = {};
        gemm_tile_p(corr0, R1T, g_M1o,       256, 512, Bt, tid, tm, tn);
        gemm_tile_p(corr1, R1T, g_M1o + 128, 256, 512, Bt, tid, tm, tn);

        #pragma unroll 1
        for (int p = 0; p < 4; p++) {
            ull u2a[8] = {};
            gemm_tile_p(u2a, R1T, g_M12 + p*128, 512, 512, Bt, tid, tm, tn);
            __syncthreads();   // previous panel's R2T readers done
            #pragma unroll
            for (int i = 0; i < 4; i++) {
                int r = tm*4 + i;
                float4 gv = *(const float4*)(g_A2g + (size_t)(k0 + r)*512 + p*128 + tn*4);
                float4 tv = *(const float4*)(a2t + p*128 + tn*4);
                float2 ua = ull2f2(u2a[2*i]);
                float2 ub = ull2f2(u2a[2*i+1]);
                int cb = tn*4;
                R2T[(cb+0)*34 + r] = fmaxf(ua.x + gv.x + tv.x, 0.f);
                R2T[(cb+1)*34 + r] = fmaxf(ua.y + gv.y + tv.y, 0.f);
                R2T[(cb+2)*34 + r] = fmaxf(ub.x + gv.z + tv.z, 0.f);
                R2T[(cb+3)*34 + r] = fmaxf(ub.y + gv.w + tv.w, 0.f);
            }
            gemm_tile_p(corr0, R2T, g_M2o + (size_t)p*128*256,       256, 128, Bt, tid, tm, tn);
            gemm_tile_p(corr1, R2T, g_M2o + (size_t)p*128*256 + 128, 256, 128, Bt, tid, tm, tn);
        }

        // distances for the 32 rows of this tile
        float part[4] = {};
        #pragma unroll
        for (int i = 0; i < 4; i++) {
            int r = tm*4 + i;
            float4 og0 = *(const float4*)(g_Og + (size_t)(k0 + r)*256 + tn*4);
            float4 og1 = *(const float4*)(g_Og + (size_t)(k0 + r)*256 + 128 + tn*4);
            float4 ox0 = *(const float4*)(otx + tn*4);
            float4 ox1 = *(const float4*)(otx + 128 + tn*4);
            float2 c0a = ull2f2(corr0[2*i]);
            float2 c0b = ull2f2(corr0[2*i+1]);
            float2 c1a = ull2f2(corr1[2*i]);
            float2 c1b = ull2f2(corr1[2*i+1]);
            float v;
            v = og0.x + ox0.x + c0a.x; part[i] += v*v;
            v = og0.y + ox0.y + c0a.y; part[i] += v*v;
            v = og0.z + ox0.z + c0b.x; part[i] += v*v;
            v = og0.w + ox0.w + c0b.y; part[i] += v*v;
            v = og1.x + ox1.x + c1a.x; part[i] += v*v;
            v = og1.y + ox1.y + c1a.y; part[i] += v*v;
            v = og1.z + ox1.z + c1b.x; part[i] += v*v;
            v = og1.w + ox1.w + c1b.y; part[i] += v*v;
        }
        #pragma unroll
        for (int i = 0; i < 4; i++) {
            #pragma unroll
            for (int off = 16; off > 0; off >>= 1)
                part[i] += __shfl_xor_sync(0xffffffffu, part[i], off);
        }
        if (tn == 0) {
            #pragma unroll
            for (int i = 0; i < 4; i++)
                g_dists[(size_t)b*2048 + f*256 + k0 + tm*4 + i] = part[i];
        }
    }
}

// -------------------- argmin per b (first occurrence on ties) ---------------
__global__ __launch_bounds__(256) void argmin_kernel()
{
    __shared__ float sv[256];
    __shared__ int   si[256];
    int b = blockIdx.x, tid = threadIdx.x;
    float best = 3.4e38f; int bi = 1 << 30;
    for (int i = tid; i < 2048; i += 256) {
        float v = g_dists[(size_t)b*2048 + i];
        if (v < best || (v == best && i < bi)) { best = v; bi = i; }
    }
    sv[tid] = best; si[tid] = bi;
    __syncthreads();
    for (int s = 128; s > 0; s >>= 1) {
        if (tid < s) {
            if (sv[tid+s] < sv[tid] || (sv[tid+s] == sv[tid] && si[tid+s] < si[tid])) {
                sv[tid] = sv[tid+s]; si[tid] = si[tid+s];
            }
        }
        __syncthreads();
    }
    if (tid == 0) g_idx[b] = si[0];
}

// -------------------- winner recompute + output -----------------------------
__global__ __launch_bounds__(512) void final_kernel(float* __restrict__ out)
{
    __shared__ float r1[512], r2[512];
    __shared__ int sIdx;
    int b = blockIdx.x, tid = threadIdx.x;
    if (tid == 0) sIdx = g_idx[b];
    __syncthreads();
    int idx = sIdx;
    int f = idx >> 8, k = idx & 255;
    int bf = b*8 + f;

    r1[tid] = fmaxf(g_A1g[(size_t)k*512 + tid] + g_A1t[(size_t)bf*512 + tid], 0.f);
    __syncthreads();
    {
        float s = g_A2g[(size_t)k*512 + tid] + g_A2t[(size_t)bf*512 + tid];
        for (int i = 0; i < 512; i++) s += r1[i] * g_M12[(size_t)i*512 + tid];
        r2[tid] = fmaxf(s, 0.f);
    }
    __syncthreads();
    if (tid < 256) {
        float s = g_Og[(size_t)k*256 + tid] + g_Ot[(size_t)bf*256 + tid];
        for (int i = 0; i < 512; i++)
            s += r1[i] * g_M1o[(size_t)i*256 + tid] + r2[i] * g_M2o[(size_t)i*256 + tid];
        out[b*256 + tid] = s;
    }
}

// codes region: floats [32768:33152] = [codes_MBF (256 int32->float), idx (128->float)]
__global__ void codes_kernel(const int* __restrict__ codes, float* __restrict__ out)
{
    int t = threadIdx.x;
    float* oc = out + Bb * Dd;
    if (t < 256)      oc[t] = (float)codes[t];
    else if (t < 384) oc[t] = (float)g_idx[t - 256];
}

// -------------------- launch ------------------------------------------------
extern "C" void kernel_launch(void* const* d_in, const int* in_sizes, int n_in,
                              void* d_out, int out_size)
{
    const float* x        = (const float*)d_in[0];
    const float* xhat     = (const float*)d_in[1];
    const int*   codes    = (const int*)d_in[2];   // int32
    const float* codebook = (const float*)d_in[3];
    const float* W_in     = (const float*)d_in[4];
    const float* b_in     = (const float*)d_in[5];
    const float* W_cat    = (const float*)d_in[6];
    const float* b_cat    = (const float*)d_in[7];
    const float* W1       = (const float*)d_in[8];
    const float* b1       = (const float*)d_in[9];
    const float* W2       = (const float*)d_in[10];
    const float* b2       = (const float*)d_in[11];
    const float* W_out    = (const float*)d_in[12];
    const float* b_out    = (const float*)d_in[13];
    float* out = (float*)d_out;

    float *p_h0, *p_g, *p_t, *p_A1g, *p_A2g, *p_A1t, *p_A2t, *p_Og, *p_Ot;
    float *p_M12, *p_M1o, *p_M2o, *p_bu2, *p_bo;
    cudaGetSymbolAddress((void**)&p_h0,  g_h0);
    cudaGetSymbolAddress((void**)&p_g,   g_g);
    cudaGetSymbolAddress((void**)&p_t,   g_t);
    cudaGetSymbolAddress((void**)&p_A1g, g_A1g);
    cudaGetSymbolAddress((void**)&p_A2g, g_A2g);
    cudaGetSymbolAddress((void**)&p_A1t, g_A1t);
    cudaGetSymbolAddress((void**)&p_A2t, g_A2t);
    cudaGetSymbolAddress((void**)&p_Og,  g_Og);
    cudaGetSymbolAddress((void**)&p_Ot,  g_Ot);
    cudaGetSymbolAddress((void**)&p_M12, g_M12);
    cudaGetSymbolAddress((void**)&p_M1o, g_M1o);
    cudaGetSymbolAddress((void**)&p_M2o, g_M2o);
    cudaGetSymbolAddress((void**)&p_bu2, g_bu2);
    cudaGetSymbolAddress((void**)&p_bo,  g_bo);

    const float* W1_0 = W1;                const float* W1_1 = W1 + 256*512;
    const float* W2_0 = W2;                const float* W2_1 = W2 + 512*256;
    const float* Wc   = W_cat;             const float* Wx   = W_cat + 256*256;
    const float* b1_1 = b1 + 512;
    const float* b2_0 = b2;                const float* b2_1 = b2 + 256;

    // bias folds: bu2 = b1[1] + b2[0]@W1[1] ; bo = b_out + (b2[0]+b2[1])@W_out
    vecmat_bias<<<2, 256>>>(p_bu2, b1_1, b2_0, nullptr, W1_1, 256, 512);
    vecmat_bias<<<1, 256>>>(p_bo,  b_out, b2_0, b2_1,   W_out, 256, 256);

    // precompute GEMMs
    sgemm64<<<dim3(4, 4),  256>>>(codebook, W_in,  p_h0,  256, 256, 256, b_in,  nullptr);
    sgemm64<<<dim3(4, 4),  256>>>(p_h0,     Wc,    p_g,   256, 256, 256, nullptr, nullptr);
    sgemm64<<<dim3(4, 16), 256>>>(xhat,     Wx,    p_t,  1024, 256, 256, b_cat, nullptr);
    sgemm64<<<dim3(8, 4),  256>>>(p_g,      W1_0,  p_A1g, 256, 512, 256, nullptr, nullptr);
    sgemm64<<<dim3(8, 16), 256>>>(p_t,      W1_0,  p_A1t,1024, 512, 256, b1,    nullptr);
    sgemm64<<<dim3(8, 4),  256>>>(p_g,      W1_1,  p_A2g, 256, 512, 256, nullptr, nullptr);
    sgemm64<<<dim3(8, 16), 256>>>(p_t,      W1_1,  p_A2t,1024, 512, 256, p_bu2, nullptr);
    sgemm64<<<dim3(4, 4),  256>>>(p_g,      W_out, p_Og,  256, 256, 256, nullptr, codebook);
    sgemm64<<<dim3(4, 16), 256>>>(p_t,      W_out, p_Ot, 1024, 256, 256, p_bo,  xhat);
    sgemm64<<<dim3(8, 8),  256>>>(W2_0,     W1_1,  p_M12, 512, 512, 256, nullptr, nullptr);
    sgemm64<<<dim3(4, 8),  256>>>(W2_0,     W_out, p_M1o, 512, 256, 256, nullptr, nullptr);
    sgemm64<<<dim3(4, 8),  256>>>(W2_1,     W_out, p_M2o, 512, 256, 256, nullptr, nullptr);

    // main distance pass (FFMA2)
    const int smem_bytes = DIST_SMEM_FLOATS * (int)sizeof(float);  // 108544
    cudaFuncSetAttribute(dist_kernel, cudaFuncAttributeMaxDynamicSharedMemorySize, smem_bytes);
    dist_kernel<<<Bb * Ff, 256, smem_bytes>>>(x);

    argmin_kernel<<<Bb, 256>>>();
    final_kernel<<<Bb, 512>>>(out);
    codes_kernel<<<1, 384>>>(codes, out);
}

// round 7
// speedup vs baseline: 1.6630x; 1.6622x over previous
#include <cuda_runtime.h>
#include <cuda_bf16.h>
#include <cstdint>

#define Bb 128
#define Ff 8
#define Kk 256
#define Dd 256
#define Hh 256
#define HFF 512
#define CAND_CAP 512
#define DELTA 2.5f
typedef unsigned long long ull;

__device__ float g_h0 [Kk*Hh];
__device__ float g_g  [Kk*Hh];
__device__ float g_t  [Bb*Ff*Hh];
__device__ float g_A1g[Kk*HFF];
__device__ float g_A2g[Kk*HFF];
__device__ float g_A1t[Bb*Ff*HFF];
__device__ float g_A2t[Bb*Ff*HFF];
__device__ float g_Og [Kk*Dd];
__device__ float g_Ot [Bb*Ff*Dd];
__device__ float g_M12[HFF*HFF];
__device__ float g_M1o[HFF*Dd];
__device__ float g_M2o[HFF*Dd];
__device__ float g_bu2[HFF];
__device__ float g_bo [Dd];
__device__ float g_dists[Bb*Ff*Kk];
__device__ __align__(16) __nv_bfloat16 g_M12b[HFF*HFF];
__device__ __align__(16) __nv_bfloat16 g_M1ob[Dd*HFF];
__device__ __align__(16) __nv_bfloat16 g_M2ob[Dd*HFF];
__device__ int  g_cnum[Bb];
__device__ int  g_clist[Bb*CAND_CAP];
__device__ ull  g_best[Bb];

// ---------------- precompute SGEMM (verified R3) -----------------------------
__global__ __launch_bounds__(256) void sgemm64(
    const float* __restrict__ A, const float* __restrict__ B, float* __restrict__ C,
    int M, int N, int K, const float* __restrict__ bias, const float* __restrict__ add)
{
    __shared__ float As[16][65];
    __shared__ float Bs[16][64];
    const int m0 = blockIdx.y * 64, n0 = blockIdx.x * 64;
    const int tid = threadIdx.x, tx = tid & 15, ty = tid >> 4;
    float acc[4][4] = {};
    for (int k0 = 0; k0 < K; k0 += 16) {
        int ra = tid >> 2, ca = (tid & 3) * 4;
        float4 av = *(const float4*)(A + (size_t)(m0 + ra) * K + k0 + ca);
        As[ca+0][ra] = av.x; As[ca+1][ra] = av.y; As[ca+2][ra] = av.z; As[ca+3][ra] = av.w;
        int rb = tid >> 4, cb = (tid & 15) * 4;
        *(float4*)&Bs[rb][cb] = *(const float4*)(B + (size_t)(k0 + rb) * N + n0 + cb);
        __syncthreads();
        #pragma unroll
        for (int kk = 0; kk < 16; kk++) {
            float a0 = As[kk][ty*4+0], a1 = As[kk][ty*4+1];
            float a2 = As[kk][ty*4+2], a3 = As[kk][ty*4+3];
            float4 bv = *(float4*)&Bs[kk][tx*4];
            acc[0][0]+=a0*bv.x; acc[0][1]+=a0*bv.y; acc[0][2]+=a0*bv.z; acc[0][3]+=a0*bv.w;
            acc[1][0]+=a1*bv.x; acc[1][1]+=a1*bv.y; acc[1][2]+=a1*bv.z; acc[1][3]+=a1*bv.w;
            acc[2][0]+=a2*bv.x; acc[2][1]+=a2*bv.y; acc[2][2]+=a2*bv.z; acc[2][3]+=a2*bv.w;
            acc[3][0]+=a3*bv.x; acc[3][1]+=a3*bv.y; acc[3][2]+=a3*bv.z; acc[3][3]+=a3*bv.w;
        }
        __syncthreads();
    }
    #pragma unroll
    for (int i = 0; i < 4; i++)
        #pragma unroll
        for (int j = 0; j < 4; j++) {
            int m = m0 + ty*4 + i, n = n0 + tx*4 + j;
            float v = acc[i][j];
            if (bias) v += bias[n];
            if (add)  v += add[(size_t)m * N + n];
            C[(size_t)m * N + n] = v;
        }
}

__global__ void vecmat_bias(float* __restrict__ out, const float* __restrict__ base,
                            const float* __restrict__ v1, const float* __restrict__ v2,
                            const float* __restrict__ Mat, int K, int N)
{
    int j = blockIdx.x * blockDim.x + threadIdx.x;
    if (j >= N) return;
    float s = base[j];
    for (int i = 0; i < K; i++) { float v = v1[i]; if (v2) v += v2[i]; s += v * Mat[(size_t)i*N + j]; }
    out[j] = s;
}

// fp32 [K][N] -> bf16 [N][K]
__global__ void convT(const float* __restrict__ src, __nv_bfloat16* __restrict__ dst, int K, int N)
{
    int idx = blockIdx.x * 256 + threadIdx.x;
    if (idx >= N * K) return;
    int n = idx / K, k = idx - n * K;
    dst[idx] = __float2bfloat16(src[(size_t)k * N + n]);
}

// ---------------- tensor-core distance kernel --------------------------------
#define RS1 520
#define WTS 72
#define SO_R1  0
#define SO_R2  66560
#define SO_WT  133120
#define SO_A2T 169984
#define SO_OTX 172032
#define SO_SD  173056
#define SMEM_DIST_BYTES 173568

__device__ __forceinline__ void mma_bf16(float* c, uint a0, uint a1, uint a2, uint a3,
                                         uint b0, uint b1)
{
    asm volatile(
        "mma.sync.aligned.m16n8k16.row.col.f32.bf16.bf16.f32 "
        "{%0,%1,%2,%3}, {%4,%5,%6,%7}, {%8,%9}, {%0,%1,%2,%3};"
        : "+f"(c[0]), "+f"(c[1]), "+f"(c[2]), "+f"(c[3])
        : "r"(a0), "r"(a1), "r"(a2), "r"(a3), "r"(b0), "r"(b1));
}

// acc[32] += Asm[64 rows x 512 k bf16, stride RS1] @ Wg[128 n][512 k]^T
__device__ __forceinline__ void gemm_pass(
    float* __restrict__ acc, const __nv_bfloat16* __restrict__ Asm,
    const __nv_bfloat16* __restrict__ Wg, __nv_bfloat16* __restrict__ wt,
    int tid, int rowA, int ngbase, int t)
{
    const int nl = tid >> 1, seg = tid & 1, g = (tid & 31) >> 2;
    const __nv_bfloat16* gsrc = Wg + nl * 512 + seg * 32;
    uint4 p0 = *(const uint4*)(gsrc),      p1 = *(const uint4*)(gsrc + 8);
    uint4 p2 = *(const uint4*)(gsrc + 16), p3 = *(const uint4*)(gsrc + 24);
    {
        __nv_bfloat16* d = wt + nl * WTS + seg * 32;
        *(uint4*)(d) = p0; *(uint4*)(d+8) = p1; *(uint4*)(d+16) = p2; *(uint4*)(d+24) = p3;
    }
    __syncthreads();
    #pragma unroll 1
    for (int c = 0; c < 8; c++) {
        if (c < 7) {
            const __nv_bfloat16* gs = gsrc + (c + 1) * 64;
            p0 = *(const uint4*)(gs);      p1 = *(const uint4*)(gs + 8);
            p2 = *(const uint4*)(gs + 16); p3 = *(const uint4*)(gs + 24);
        }
        const __nv_bfloat16* tb = wt + (c & 1) * (128 * WTS);
        #pragma unroll
        for (int ks = 0; ks < 4; ks++) {
            const int kA = c * 64 + ks * 16;
            uint a0 = *(const uint*)(Asm + (size_t)rowA * RS1 + kA + 2*t);
            uint a1 = *(const uint*)(Asm + (size_t)(rowA+8) * RS1 + kA + 2*t);
            uint a2 = *(const uint*)(Asm + (size_t)rowA * RS1 + kA + 2*t + 8);
            uint a3 = *(const uint*)(Asm + (size_t)(rowA+8) * RS1 + kA + 2*t + 8);
            const __nv_bfloat16* bbase = tb + ks * 16 + 2*t;
            #pragma unroll
            for (int j = 0; j < 8; j++) {
                const __nv_bfloat16* bp = bbase + (ngbase + j*8 + g) * WTS;
                mma_bf16(acc + j*4, a0, a1, a2, a3, *(const uint*)bp, *(const uint*)(bp + 8));
            }
        }
        __syncthreads();
        if (c < 7) {
            __nv_bfloat16* d = wt + ((c+1) & 1) * (128 * WTS) + nl * WTS + seg * 32;
            *(uint4*)(d) = p0; *(uint4*)(d+8) = p1; *(uint4*)(d+16) = p2; *(uint4*)(d+24) = p3;
        }
        __syncthreads();
    }
}

__global__ __launch_bounds__(256) void dist_mma_kernel(const float* __restrict__ x)
{
    extern __shared__ char sm[];
    __nv_bfloat16* R1b = (__nv_bfloat16*)(sm + SO_R1);
    __nv_bfloat16* R2b = (__nv_bfloat16*)(sm + SO_R2);
    __nv_bfloat16* wt  = (__nv_bfloat16*)(sm + SO_WT);
    float* a2t = (float*)(sm + SO_A2T);
    float* otx = (float*)(sm + SO_OTX);
    float* sd  = (float*)(sm + SO_SD);

    const int bx = blockIdx.x;
    const int bf = bx >> 2, m0 = (bx & 3) * 64;
    const int b = bf >> 3, f = bf & 7;
    const int tid = threadIdx.x, lane = tid & 31, warp = tid >> 5;
    const int mw = warp & 3, ng = warp >> 2;
    const int g = lane >> 2, t = lane & 3;
    const int rowA = mw * 16 + g, ngbase = ng * 64;

    for (int i = tid; i < 512; i += 256) a2t[i] = g_A2t[(size_t)bf*512 + i];
    if (tid < 256) otx[tid] = g_Ot[(size_t)bf*256 + tid] - x[(size_t)b*256 + tid];

    for (int i = tid; i < 64*256; i += 256) {
        int r = i >> 8, c2 = i & 255;
        float2 av = *(const float2*)(g_A1g + (size_t)(m0 + r)*512 + 2*c2);
        float2 tv = *(const float2*)(g_A1t + (size_t)bf*512 + 2*c2);
        __nv_bfloat162 pk = __floats2bfloat162_rn(fmaxf(av.x + tv.x, 0.f), fmaxf(av.y + tv.y, 0.f));
        *(uint*)(R1b + (size_t)r*RS1 + 2*c2) = *(uint*)&pk;
    }
    __syncthreads();

    float corrA[32] = {}, corrB[32] = {};
    gemm_pass(corrA, R1b, g_M1ob,           wt, tid, rowA, ngbase, t);
    gemm_pass(corrB, R1b, g_M1ob + 128*512, wt, tid, rowA, ngbase, t);

    #pragma unroll 1
    for (int p = 0; p < 4; p++) {
        float u2[32] = {};
        gemm_pass(u2, R1b, g_M12b + (size_t)p*128*512, wt, tid, rowA, ngbase, t);
        #pragma unroll
        for (int j = 0; j < 8; j++) {
            int n = p*128 + ngbase + j*8 + 2*t;
            int r1g = m0 + rowA, r2g = r1g + 8;
            float2 gv1 = *(const float2*)(g_A2g + (size_t)r1g*512 + n);
            float2 gv2 = *(const float2*)(g_A2g + (size_t)r2g*512 + n);
            float2 tv  = *(const float2*)(a2t + n);
            __nv_bfloat162 q1 = __floats2bfloat162_rn(fmaxf(u2[j*4+0]+gv1.x+tv.x, 0.f),
                                                      fmaxf(u2[j*4+1]+gv1.y+tv.y, 0.f));
            __nv_bfloat162 q2 = __floats2bfloat162_rn(fmaxf(u2[j*4+2]+gv2.x+tv.x, 0.f),
                                                      fmaxf(u2[j*4+3]+gv2.y+tv.y, 0.f));
            *(uint*)(R2b + (size_t)rowA*RS1 + n)     = *(uint*)&q1;
            *(uint*)(R2b + (size_t)(rowA+8)*RS1 + n) = *(uint*)&q2;
        }
        __syncthreads();
    }

    gemm_pass(corrA, R2b, g_M2ob,           wt, tid, rowA, ngbase, t);
    gemm_pass(corrB, R2b, g_M2ob + 128*512, wt, tid, rowA, ngbase, t);

    float pr1 = 0.f, pr2 = 0.f;
    #pragma unroll
    for (int h = 0; h < 2; h++) {
        const float* cc = h ? corrB : corrA;
        #pragma unroll
        for (int j = 0; j < 8; j++) {
            int n = h*128 + ngbase + j*8 + 2*t;
            int r1g = m0 + rowA, r2g = r1g + 8;
            float2 og1 = *(const float2*)(g_Og + (size_t)r1g*256 + n);
            float2 og2 = *(const float2*)(g_Og + (size_t)r2g*256 + n);
            float2 ox  = *(const float2*)(otx + n);
            float w;
            w = og1.x + ox.x + cc[j*4+0]; pr1 += w*w;
            w = og1.y + ox.y + cc[j*4+1]; pr1 += w*w;
            w = og2.x + ox.x + cc[j*4+2]; pr2 += w*w;
            w = og2.y + ox.y + cc[j*4+3]; pr2 += w*w;
        }
    }
    pr1 += __shfl_xor_sync(~0u, pr1, 1); pr1 += __shfl_xor_sync(~0u, pr1, 2);
    pr2 += __shfl_xor_sync(~0u, pr2, 1); pr2 += __shfl_xor_sync(~0u, pr2, 2);
    if (t == 0) { sd[ng*64 + rowA] = pr1; sd[ng*64 + rowA + 8] = pr2; }
    __syncthreads();
    if (tid < 64)
        g_dists[(size_t)b*2048 + f*256 + m0 + tid] = sd[tid] + sd[64 + tid];
}

// ---------------- selection + exact rescore ----------------------------------
__global__ void initsel_kernel()
{
    int t = threadIdx.x;
    if (t < Bb) { g_cnum[t] = 0; g_best[t] = ~0ull; }
}

__global__ __launch_bounds__(256) void selcollect_kernel()
{
    __shared__ float sv[256];
    int b = blockIdx.x, tid = threadIdx.x;
    float best = 3.4e38f;
    for (int i = tid; i < 2048; i += 256) best = fminf(best, g_dists[(size_t)b*2048 + i]);
    sv[tid] = best; __syncthreads();
    for (int s = 128; s > 0; s >>= 1) { if (tid < s) sv[tid] = fminf(sv[tid], sv[tid+s]); __syncthreads(); }
    float thr = sv[0] + DELTA;
    for (int i = tid; i < 2048; i += 256)
        if (g_dists[(size_t)b*2048 + i] <= thr) {
            int pos = atomicAdd(&g_cnum[b], 1);
            if (pos < CAND_CAP) g_clist[b*CAND_CAP + pos] = i;
        }
}

__global__ __launch_bounds__(256) void rescore_kernel(const float* __restrict__ x)
{
    __shared__ float r1s[512], r2s[512], red[256];
    const int tid = threadIdx.x;
    for (int slot = blockIdx.x; slot < Bb * CAND_CAP; slot += 2048) {
        int b = slot / CAND_CAP, j = slot - b * CAND_CAP;
        int cnt = g_cnum[b]; if (cnt > CAND_CAP) cnt = CAND_CAP;
        if (j >= cnt) continue;
        int fi = g_clist[b*CAND_CAP + j];
        int f = fi >> 8, k = fi & 255, bf = b*8 + f;
        for (int q = tid; q < 512; q += 256)
            r1s[q] = fmaxf(g_A1g[(size_t)k*512 + q] + g_A1t[(size_t)bf*512 + q], 0.f);
        __syncthreads();
        for (int q = tid; q < 512; q += 256) {
            float s = g_A2g[(size_t)k*512 + q] + g_A2t[(size_t)bf*512 + q];
            for (int i = 0; i < 512; i++) s += r1s[i] * g_M12[(size_t)i*512 + q];
            r2s[q] = fmaxf(s, 0.f);
        }
        __syncthreads();
        {
            int c = tid;
            float s = g_Og[(size_t)k*256 + c] + g_Ot[(size_t)bf*256 + c] - x[(size_t)b*256 + c];
            for (int i = 0; i < 512; i++)
                s += r1s[i] * g_M1o[(size_t)i*256 + c] + r2s[i] * g_M2o[(size_t)i*256 + c];
            red[tid] = s * s;
        }
        __syncthreads();
        for (int s2 = 128; s2 > 0; s2 >>= 1) { if (tid < s2) red[tid] += red[tid+s2]; __syncthreads(); }
        if (tid == 0) {
            ull key = ((ull)__float_as_uint(red[0]) << 32) | (uint)fi;
            atomicMin(&g_best[b], key);
        }
        __syncthreads();
    }
}

// ---------------- winner recompute + output ----------------------------------
__global__ __launch_bounds__(512) void final_kernel(float* __restrict__ out)
{
    __shared__ float r1[512], r2[512];
    __shared__ int sIdx;
    int b = blockIdx.x, tid = threadIdx.x;
    if (tid == 0) sIdx = (int)(g_best[b] & 0xffffffffu);
    __syncthreads();
    int idx = sIdx, f = idx >> 8, k = idx & 255, bf = b*8 + f;
    r1[tid] = fmaxf(g_A1g[(size_t)k*512 + tid] + g_A1t[(size_t)bf*512 + tid], 0.f);
    __syncthreads();
    {
        float s = g_A2g[(size_t)k*512 + tid] + g_A2t[(size_t)bf*512 + tid];
        for (int i = 0; i < 512; i++) s += r1[i] * g_M12[(size_t)i*512 + tid];
        r2[tid] = fmaxf(s, 0.f);
    }
    __syncthreads();
    if (tid < 256) {
        float s = g_Og[(size_t)k*256 + tid] + g_Ot[(size_t)bf*256 + tid];
        for (int i = 0; i < 512; i++)
            s += r1[i] * g_M1o[(size_t)i*256 + tid] + r2[i] * g_M2o[(size_t)i*256 + tid];
        out[b*256 + tid] = s;
    }
}

__global__ void codes_kernel(const int* __restrict__ codes, float* __restrict__ out)
{
    int t = threadIdx.x;
    float* oc = out + Bb * Dd;
    if (t < 256)      oc[t] = (float)codes[t];
    else if (t < 384) oc[t] = (float)(g_best[t - 256] & 0xffffffffu);
}

// ---------------- launch ------------------------------------------------------
extern "C" void kernel_launch(void* const* d_in, const int* in_sizes, int n_in,
                              void* d_out, int out_size)
{
    const float* x        = (const float*)d_in[0];
    const float* xhat     = (const float*)d_in[1];
    const int*   codes    = (const int*)d_in[2];
    const float* codebook = (const float*)d_in[3];
    const float* W_in     = (const float*)d_in[4];
    const float* b_in     = (const float*)d_in[5];
    const float* W_cat    = (const float*)d_in[6];
    const float* b_cat    = (const float*)d_in[7];
    const float* W1       = (const float*)d_in[8];
    const float* b1       = (const float*)d_in[9];
    const float* W2       = (const float*)d_in[10];
    const float* b2       = (const float*)d_in[11];
    const float* W_out    = (const float*)d_in[12];
    const float* b_out    = (const float*)d_in[13];
    float* out = (float*)d_out;

    float *p_h0,*p_g,*p_t,*p_A1g,*p_A2g,*p_A1t,*p_A2t,*p_Og,*p_Ot,*p_M12,*p_M1o,*p_M2o,*p_bu2,*p_bo;
    __nv_bfloat16 *p_M12b, *p_M1ob, *p_M2ob;
    cudaGetSymbolAddress((void**)&p_h0,  g_h0);
    cudaGetSymbolAddress((void**)&p_g,   g_g);
    cudaGetSymbolAddress((void**)&p_t,   g_t);
    cudaGetSymbolAddress((void**)&p_A1g, g_A1g);
    cudaGetSymbolAddress((void**)&p_A2g, g_A2g);
    cudaGetSymbolAddress((void**)&p_A1t, g_A1t);
    cudaGetSymbolAddress((void**)&p_A2t, g_A2t);
    cudaGetSymbolAddress((void**)&p_Og,  g_Og);
    cudaGetSymbolAddress((void**)&p_Ot,  g_Ot);
    cudaGetSymbolAddress((void**)&p_M12, g_M12);
    cudaGetSymbolAddress((void**)&p_M1o, g_M1o);
    cudaGetSymbolAddress((void**)&p_M2o, g_M2o);
    cudaGetSymbolAddress((void**)&p_bu2, g_bu2);
    cudaGetSymbolAddress((void**)&p_bo,  g_bo);
    cudaGetSymbolAddress((void**)&p_M12b, g_M12b);
    cudaGetSymbolAddress((void**)&p_M1ob, g_M1ob);
    cudaGetSymbolAddress((void**)&p_M2ob, g_M2ob);

    const float* W1_0 = W1;     const float* W1_1 = W1 + 256*512;
    const float* W2_0 = W2;     const float* W2_1 = W2 + 512*256;
    const float* Wc   = W_cat;  const float* Wx   = W_cat + 256*256;
    const float* b1_1 = b1 + 512;
    const float* b2_0 = b2;     const float* b2_1 = b2 + 256;

    vecmat_bias<<<2, 256>>>(p_bu2, b1_1, b2_0, nullptr, W1_1, 256, 512);
    vecmat_bias<<<1, 256>>>(p_bo,  b_out, b2_0, b2_1,   W_out, 256, 256);

    sgemm64<<<dim3(4, 4),  256>>>(codebook, W_in,  p_h0,  256, 256, 256, b_in,  nullptr);
    sgemm64<<<dim3(4, 4),  256>>>(p_h0,     Wc,    p_g,   256, 256, 256, nullptr, nullptr);
    sgemm64<<<dim3(4, 16), 256>>>(xhat,     Wx,    p_t,  1024, 256, 256, b_cat, nullptr);
    sgemm64<<<dim3(8, 4),  256>>>(p_g,      W1_0,  p_A1g, 256, 512, 256, nullptr, nullptr);
    sgemm64<<<dim3(8, 16), 256>>>(p_t,      W1_0,  p_A1t,1024, 512, 256, b1,    nullptr);
    sgemm64<<<dim3(8, 4),  256>>>(p_g,      W1_1,  p_A2g, 256, 512, 256, nullptr, nullptr);
    sgemm64<<<dim3(8, 16), 256>>>(p_t,      W1_1,  p_A2t,1024, 512, 256, p_bu2, nullptr);
    sgemm64<<<dim3(4, 4),  256>>>(p_g,      W_out, p_Og,  256, 256, 256, nullptr, codebook);
    sgemm64<<<dim3(4, 16), 256>>>(p_t,      W_out, p_Ot, 1024, 256, 256, p_bo,  xhat);
    sgemm64<<<dim3(8, 8),  256>>>(W2_0,     W1_1,  p_M12, 512, 512, 256, nullptr, nullptr);
    sgemm64<<<dim3(4, 8),  256>>>(W2_0,     W_out, p_M1o, 512, 256, 256, nullptr, nullptr);
    sgemm64<<<dim3(4, 8),  256>>>(W2_1,     W_out, p_M2o, 512, 256, 256, nullptr, nullptr);

    convT<<<1024, 256>>>(p_M12, p_M12b, 512, 512);
    convT<<<512,  256>>>(p_M1o, p_M1ob, 512, 256);
    convT<<<512,  256>>>(p_M2o, p_M2ob, 512, 256);

    initsel_kernel<<<1, 128>>>();

    cudaFuncSetAttribute(dist_mma_kernel, cudaFuncAttributeMaxDynamicSharedMemorySize, SMEM_DIST_BYTES);
    dist_mma_kernel<<<Bb * Ff * 4, 256, SMEM_DIST_BYTES>>>(x);

    selcollect_kernel<<<Bb, 256>>>();
    rescore_kernel<<<2048, 256>>>(x);
    final_kernel<<<Bb, 512>>>(out);
    codes_kernel<<<1, 384>>>(codes, out);
}

// round 9
// speedup vs baseline: 1.8421x; 1.1077x over previous
#include <cuda_runtime.h>
#include <cuda_bf16.h>
#include <cstdint>

#define Bb 128
#define Ff 8
#define Kk 256
#define Dd 256
#define Hh 256
#define HFF 512
#define CAND_CAP 512
#define DELTA 2.5f
typedef unsigned long long ull;

// ---------------- device scratch ---------------------------------------------
__device__ float g_h0 [Kk*Hh];
__device__ float g_g  [Kk*Hh];
__device__ float g_t  [Bb*Ff*Hh];
__device__ float g_A1g[Kk*HFF];
__device__ float g_A2g[Kk*HFF];
__device__ float g_A1t[Bb*Ff*HFF];
__device__ float g_A2t[Bb*Ff*HFF];
__device__ float g_Og [Kk*Dd];
__device__ float g_Ot [Bb*Ff*Dd];
__device__ float g_M12[HFF*HFF];
__device__ float g_M1o[HFF*Dd];
__device__ float g_M2o[HFF*Dd];
__device__ float g_bu2[HFF];
__device__ float g_bo [Dd];
__device__ float g_dists[Bb*Ff*Kk];
// bf16 weights transposed to [N][K]
__device__ __align__(16) __nv_bfloat16 g_M12b[HFF*HFF];
__device__ __align__(16) __nv_bfloat16 g_M1ob[Dd*HFF];
__device__ __align__(16) __nv_bfloat16 g_M2ob[Dd*HFF];
__device__ int  g_cnum[Bb];
__device__ int  g_clist[Bb*CAND_CAP];
__device__ ull  g_best[Bb];

// ---------------- helpers ------------------------------------------------------
__device__ __forceinline__ uint32_t smem_to_u32(const void* p) {
    uint32_t a;
    asm("{ .reg .u64 t; cvta.to.shared.u64 t, %1; cvt.u32.u64 %0, t; }" : "=r"(a) : "l"(p));
    return a;
}
__device__ __forceinline__ void mma_bf16(float* c, uint32_t a0, uint32_t a1, uint32_t a2,
                                         uint32_t a3, uint32_t b0, uint32_t b1)
{
    asm volatile(
        "mma.sync.aligned.m16n8k16.row.col.f32.bf16.bf16.f32 "
        "{%0,%1,%2,%3}, {%4,%5,%6,%7}, {%8,%9}, {%0,%1,%2,%3};"
        : "+f"(c[0]), "+f"(c[1]), "+f"(c[2]), "+f"(c[3])
        : "r"(a0), "r"(a1), "r"(a2), "r"(a3), "r"(b0), "r"(b1));
}
__device__ __forceinline__ void ldsm4(uint32_t& r0, uint32_t& r1, uint32_t& r2, uint32_t& r3,
                                      uint32_t addr)
{
    asm volatile("ldmatrix.sync.aligned.m8n8.x4.shared.b16 {%0,%1,%2,%3}, [%4];"
        : "=r"(r0), "=r"(r1), "=r"(r2), "=r"(r3) : "r"(addr));
}
__device__ __forceinline__ void cpasync16(uint32_t dst, const void* src)
{
    asm volatile("cp.async.cg.shared.global [%0], [%1], 16;" :: "r"(dst), "l"(src) : "memory");
}

// ---------------- precompute kernels (verified R3/R7) --------------------------
__global__ __launch_bounds__(256) void sgemm64(
    const float* __restrict__ A, const float* __restrict__ B, float* __restrict__ C,
    int M, int N, int K, const float* __restrict__ bias, const float* __restrict__ add)
{
    __shared__ float As[16][65];
    __shared__ float Bs[16][64];
    const int m0 = blockIdx.y * 64, n0 = blockIdx.x * 64;
    const int tid = threadIdx.x, tx = tid & 15, ty = tid >> 4;
    float acc[4][4] = {};
    for (int k0 = 0; k0 < K; k0 += 16) {
        int ra = tid >> 2, ca = (tid & 3) * 4;
        float4 av = *(const float4*)(A + (size_t)(m0 + ra) * K + k0 + ca);
        As[ca+0][ra] = av.x; As[ca+1][ra] = av.y; As[ca+2][ra] = av.z; As[ca+3][ra] = av.w;
        int rb = tid >> 4, cb = (tid & 15) * 4;
        *(float4*)&Bs[rb][cb] = *(const float4*)(B + (size_t)(k0 + rb) * N + n0 + cb);
        __syncthreads();
        #pragma unroll
        for (int kk = 0; kk < 16; kk++) {
            float a0 = As[kk][ty*4+0], a1 = As[kk][ty*4+1];
            float a2 = As[kk][ty*4+2], a3 = As[kk][ty*4+3];
            float4 bv = *(float4*)&Bs[kk][tx*4];
            acc[0][0]+=a0*bv.x; acc[0][1]+=a0*bv.y; acc[0][2]+=a0*bv.z; acc[0][3]+=a0*bv.w;
            acc[1][0]+=a1*bv.x; acc[1][1]+=a1*bv.y; acc[1][2]+=a1*bv.z; acc[1][3]+=a1*bv.w;
            acc[2][0]+=a2*bv.x; acc[2][1]+=a2*bv.y; acc[2][2]+=a2*bv.z; acc[2][3]+=a2*bv.w;
            acc[3][0]+=a3*bv.x; acc[3][1]+=a3*bv.y; acc[3][2]+=a3*bv.z; acc[3][3]+=a3*bv.w;
        }
        __syncthreads();
    }
    #pragma unroll
    for (int i = 0; i < 4; i++)
        #pragma unroll
        for (int j = 0; j < 4; j++) {
            int m = m0 + ty*4 + i, n = n0 + tx*4 + j;
            float v = acc[i][j];
            if (bias) v += bias[n];
            if (add)  v += add[(size_t)m * N + n];
            C[(size_t)m * N + n] = v;
        }
}

__global__ void vecmat_bias(float* __restrict__ out, const float* __restrict__ base,
                            const float* __restrict__ v1, const float* __restrict__ v2,
                            const float* __restrict__ Mat, int K, int N)
{
    int j = blockIdx.x * blockDim.x + threadIdx.x;
    if (j >= N) return;
    float s = base[j];
    for (int i = 0; i < K; i++) { float v = v1[i]; if (v2) v += v2[i]; s += v * Mat[(size_t)i*N + j]; }
    out[j] = s;
}

// fp32 [K][N] -> bf16 [N][K]
__global__ void convT(const float* __restrict__ src, __nv_bfloat16* __restrict__ dst, int K, int N)
{
    int idx = blockIdx.x * 256 + threadIdx.x;
    if (idx >= N * K) return;
    int n = idx / K, k = idx - n * K;
    dst[idx] = __float2bfloat16(src[(size_t)k * N + n]);
}

// ---------------- mma distance kernel ------------------------------------------
// CTA: one (bf, 64-code m-tile). grid 4096, 256 threads (warps: mw 0..3 x ng 0..1).
// A tiles (R1/R2): [64 m][520 k] bf16 (stride 1040B = 16 mod 128 -> LDSM clean).
// Weight chunks: [128 n][136 k-pad] bf16 (stride 272B), 32KB, cp.async double-buffered.
#define RS1 520
#define WTR 136
#define TS_A1T 0
#define TS_A2T 2048
#define TS_OTX 4096
#define TS_R1  5120
#define TS_R2  71680
#define TS_WT0 138240
#define TS_WT1 173056
#define TS_TOTAL 207872

__device__ __forceinline__ void cp_chunk(uint32_t dstbase, const __nv_bfloat16* __restrict__ W,
                                         int c, int tid)
{
    #pragma unroll
    for (int i = 0; i < 8; i++) {
        int s = tid + 256 * i;
        int n = s >> 4, ks = s & 15;
        cpasync16(dstbase + n * 272 + ks * 16, W + (size_t)n * 512 + c * 128 + ks * 8);
    }
    asm volatile("cp.async.commit_group;" ::: "memory");
}

// acc[32] += A[64x128 chunk] @ Wchunk^T  (8 k16-steps, 8 n-atoms per warp)
__device__ __forceinline__ void chunk_mma(float* __restrict__ acc, uint32_t aAddr, uint32_t bAddr)
{
    #pragma unroll
    for (int ks = 0; ks < 8; ks++) {
        uint32_t a0, a1, a2, a3;
        ldsm4(a0, a1, a2, a3, aAddr + ks * 32);
        #pragma unroll
        for (int jp = 0; jp < 4; jp++) {
            uint32_t b0, b1, b2, b3;
            ldsm4(b0, b1, b2, b3, bAddr + ks * 32 + jp * (16 * 272));
            mma_bf16(acc + jp * 8,     a0, a1, a2, a3, b0, b1);
            mma_bf16(acc + jp * 8 + 4, a0, a1, a2, a3, b2, b3);
        }
    }
}

#define STEP(ACC, AADDR, WN, CN, HAVE) do { \
    if (HAVE) { \
        cp_chunk(sb + (buf ? TS_WT0 : TS_WT1), (WN), (CN), tid); \
        asm volatile("cp.async.wait_group 1;" ::: "memory"); \
    } else { \
        asm volatile("cp.async.wait_group 0;" ::: "memory"); \
    } \
    __syncthreads(); \
    chunk_mma((ACC), (AADDR), (buf ? sb + TS_WT1 : sb + TS_WT0) + bOff); \
    __syncthreads(); \
    buf ^= 1; \
} while (0)

__global__ __launch_bounds__(256) void dist_mma2_kernel(const float* __restrict__ x)
{
    extern __shared__ char smch[];
    const uint32_t sb = smem_to_u32(smch);
    float* a1t = (float*)(smch + TS_A1T);
    float* a2t = (float*)(smch + TS_A2T);
    float* otx = (float*)(smch + TS_OTX);

    const int bx = blockIdx.x;
    const int bf = bx >> 2, m0 = (bx & 3) * 64;
    const int b = bf >> 3, f = bf & 7;
    const int tid = threadIdx.x, lane = tid & 31, warp = tid >> 5;
    const int mw = warp & 3, ng = warp >> 2;
    const int g = lane >> 2, t = lane & 3;
    const int rowA = mw * 16 + g;        // fragment row (0..63)
    const int ngbase = ng * 64;

    // per-thread ldmatrix base offsets (bytes)
    const uint32_t aOff = (uint32_t)(mw * 16 + (lane & 15)) * (RS1 * 2) + ((lane >> 4) & 1) * 16;
    const uint32_t aR1 = sb + TS_R1 + aOff;
    const uint32_t aR2 = sb + TS_R2 + aOff;
    const uint32_t bOff = (uint32_t)(ngbase + ((lane & 16) >> 1) + (lane & 7)) * 272
                        + ((lane & 8) >> 3) * 16;

    for (int i = tid; i < 512; i += 256) { a1t[i] = g_A1t[(size_t)bf*512 + i]; a2t[i] = g_A2t[(size_t)bf*512 + i]; }
    if (tid < 256) otx[tid] = g_Ot[(size_t)bf*256 + tid] - x[(size_t)b*256 + tid];
    __syncthreads();

    // R1 = relu(A1g[m0+r] + a1t)  -> [64][520] bf16
    for (int i = tid; i < 64 * 256; i += 256) {
        int r = i >> 8, c2 = i & 255;
        float2 av = *(const float2*)(g_A1g + (size_t)(m0 + r) * 512 + 2 * c2);
        float2 tv = *(const float2*)(a1t + 2 * c2);
        __nv_bfloat162 pk = __floats2bfloat162_rn(fmaxf(av.x + tv.x, 0.f), fmaxf(av.y + tv.y, 0.f));
        *(uint32_t*)(smch + TS_R1 + ((size_t)r * RS1 + 2 * c2) * 2) = *(uint32_t*)&pk;
    }
    __syncthreads();

    int buf = 0;
    cp_chunk(sb + TS_WT0, g_M12b, 0, tid);   // prefetch first chunk

    float corr[32], pr1 = 0.f, pr2 = 0.f;

    // ---- Phase A: u2 panels -> R2 ----
    for (int p = 0; p < 4; p++) {
        float u2[32];
        #pragma unroll
        for (int i = 0; i < 32; i++) u2[i] = 0.f;
        for (int c = 0; c < 4; c++) {
            const __nv_bfloat16* Wn; int cn;
            if (c < 3)      { Wn = g_M12b + (size_t)p * 65536;       cn = c + 1; }
            else if (p < 3) { Wn = g_M12b + (size_t)(p + 1) * 65536; cn = 0; }
            else            { Wn = g_M1ob;                           cn = 0; }
            STEP(u2, aR1 + c * 256, Wn, cn, 1);
        }
        // epilogue: R2 panel p = relu(u2 + A2g + a2t)
        #pragma unroll
        for (int j = 0; j < 8; j++) {
            int n = p * 128 + ngbase + j * 8 + 2 * t;
            float2 gv1 = *(const float2*)(g_A2g + (size_t)(m0 + rowA) * 512 + n);
            float2 gv2 = *(const float2*)(g_A2g + (size_t)(m0 + rowA + 8) * 512 + n);
            float2 tv  = *(const float2*)(a2t + n);
            __nv_bfloat162 q1 = __floats2bfloat162_rn(fmaxf(u2[j*4+0] + gv1.x + tv.x, 0.f),
                                                      fmaxf(u2[j*4+1] + gv1.y + tv.y, 0.f));
            __nv_bfloat162 q2 = __floats2bfloat162_rn(fmaxf(u2[j*4+2] + gv2.x + tv.x, 0.f),
                                                      fmaxf(u2[j*4+3] + gv2.y + tv.y, 0.f));
            *(uint32_t*)(smch + TS_R2 + ((size_t)rowA * RS1 + n) * 2)       = *(uint32_t*)&q1;
            *(uint32_t*)(smch + TS_R2 + ((size_t)(rowA + 8) * RS1 + n) * 2) = *(uint32_t*)&q2;
        }
    }

    // ---- Phase B: corr half 0 ----
    #pragma unroll
    for (int i = 0; i < 32; i++) corr[i] = 0.f;
    for (int c = 0; c < 4; c++) {
        const __nv_bfloat16* Wn = (c < 3) ? g_M1ob : g_M2ob;
        int cn = (c < 3) ? c + 1 : 0;
        STEP(corr, aR1 + c * 256, Wn, cn, 1);
    }
    for (int c = 0; c < 4; c++) {
        const __nv_bfloat16* Wn = (c < 3) ? g_M2ob : g_M1ob + 65536;
        int cn = (c < 3) ? c + 1 : 0;
        STEP(corr, aR2 + c * 256, Wn, cn, 1);
    }
    #pragma unroll
    for (int j = 0; j < 8; j++) {
        int n = ngbase + j * 8 + 2 * t;
        float2 og1 = *(const float2*)(g_Og + (size_t)(m0 + rowA) * 256 + n);
        float2 og2 = *(const float2*)(g_Og + (size_t)(m0 + rowA + 8) * 256 + n);
        float2 ox  = *(const float2*)(otx + n);
        float w;
        w = og1.x + ox.x + corr[j*4+0]; pr1 += w * w;
        w = og1.y + ox.y + corr[j*4+1]; pr1 += w * w;
        w = og2.x + ox.x + corr[j*4+2]; pr2 += w * w;
        w = og2.y + ox.y + corr[j*4+3]; pr2 += w * w;
    }

    // ---- Phase C: corr half 1 ----
    #pragma unroll
    for (int i = 0; i < 32; i++) corr[i] = 0.f;
    for (int c = 0; c < 4; c++) {
        const __nv_bfloat16* Wn = (c < 3) ? g_M1ob + 65536 : g_M2ob + 65536;
        int cn = (c < 3) ? c + 1 : 0;
        STEP(corr, aR1 + c * 256, Wn, cn, 1);
    }
    for (int c = 0; c < 4; c++) {
        const __nv_bfloat16* Wn = g_M2ob + 65536;
        int cn = c + 1;
        STEP(corr, aR2 + c * 256, Wn, cn, (c < 3));
    }
    #pragma unroll
    for (int j = 0; j < 8; j++) {
        int n = 128 + ngbase + j * 8 + 2 * t;
        float2 og1 = *(const float2*)(g_Og + (size_t)(m0 + rowA) * 256 + n);
        float2 og2 = *(const float2*)(g_Og + (size_t)(m0 + rowA + 8) * 256 + n);
        float2 ox  = *(const float2*)(otx + n);
        float w;
        w = og1.x + ox.x + corr[j*4+0]; pr1 += w * w;
        w = og1.y + ox.y + corr[j*4+1]; pr1 += w * w;
        w = og2.x + ox.x + corr[j*4+2]; pr2 += w * w;
        w = og2.y + ox.y + corr[j*4+3]; pr2 += w * w;
    }

    // reduce over t lanes, write
    pr1 += __shfl_xor_sync(~0u, pr1, 1); pr1 += __shfl_xor_sync(~0u, pr1, 2);
    pr2 += __shfl_xor_sync(~0u, pr2, 1); pr2 += __shfl_xor_sync(~0u, pr2, 2);
    float* sd = (float*)(smch + TS_A1T);  // reuse a1t
    __syncthreads();
    if (t == 0) { sd[ng * 64 + rowA] = pr1; sd[ng * 64 + rowA + 8] = pr2; }
    __syncthreads();
    if (tid < 64)
        g_dists[(size_t)b * 2048 + f * 256 + m0 + tid] = sd[tid] + sd[64 + tid];
}

// ---------------- selection + exact rescore (verified R7) ----------------------
__global__ void initsel_kernel()
{
    int t = threadIdx.x;
    if (t < Bb) { g_cnum[t] = 0; g_best[t] = ~0ull; }
}

__global__ __launch_bounds__(256) void selcollect_kernel()
{
    __shared__ float sv[256];
    int b = blockIdx.x, tid = threadIdx.x;
    float best = 3.4e38f;
    for (int i = tid; i < 2048; i += 256) best = fminf(best, g_dists[(size_t)b*2048 + i]);
    sv[tid] = best; __syncthreads();
    for (int s = 128; s > 0; s >>= 1) { if (tid < s) sv[tid] = fminf(sv[tid], sv[tid+s]); __syncthreads(); }
    float thr = sv[0] + DELTA;
    for (int i = tid; i < 2048; i += 256)
        if (g_dists[(size_t)b*2048 + i] <= thr) {
            int pos = atomicAdd(&g_cnum[b], 1);
            if (pos < CAND_CAP) g_clist[b*CAND_CAP + pos] = i;
        }
}

__global__ __launch_bounds__(256) void rescore_kernel(const float* __restrict__ x)
{
    __shared__ float r1s[512], r2s[512], red[256];
    const int tid = threadIdx.x;
    for (int slot = blockIdx.x; slot < Bb * CAND_CAP; slot += 2048) {
        int b = slot / CAND_CAP, j = slot - b * CAND_CAP;
        int cnt = g_cnum[b]; if (cnt > CAND_CAP) cnt = CAND_CAP;
        if (j >= cnt) continue;
        int fi = g_clist[b*CAND_CAP + j];
        int f = fi >> 8, k = fi & 255, bf = b*8 + f;
        for (int q = tid; q < 512; q += 256)
            r1s[q] = fmaxf(g_A1g[(size_t)k*512 + q] + g_A1t[(size_t)bf*512 + q], 0.f);
        __syncthreads();
        for (int q = tid; q < 512; q += 256) {
            float s = g_A2g[(size_t)k*512 + q] + g_A2t[(size_t)bf*512 + q];
            for (int i = 0; i < 512; i++) s += r1s[i] * g_M12[(size_t)i*512 + q];
            r2s[q] = fmaxf(s, 0.f);
        }
        __syncthreads();
        {
            int c = tid;
            float s = g_Og[(size_t)k*256 + c] + g_Ot[(size_t)bf*256 + c] - x[(size_t)b*256 + c];
            for (int i = 0; i < 512; i++)
                s += r1s[i] * g_M1o[(size_t)i*256 + c] + r2s[i] * g_M2o[(size_t)i*256 + c];
            red[tid] = s * s;
        }
        __syncthreads();
        for (int s2 = 128; s2 > 0; s2 >>= 1) { if (tid < s2) red[tid] += red[tid+s2]; __syncthreads(); }
        if (tid == 0) {
            ull key = ((ull)__float_as_uint(red[0]) << 32) | (uint32_t)fi;
            atomicMin(&g_best[b], key);
        }
        __syncthreads();
    }
}

__global__ __launch_bounds__(512) void final_kernel(float* __restrict__ out)
{
    __shared__ float r1[512], r2[512];
    __shared__ int sIdx;
    int b = blockIdx.x, tid = threadIdx.x;
    if (tid == 0) sIdx = (int)(g_best[b] & 0xffffffffu);
    __syncthreads();
    int idx = sIdx, f = idx >> 8, k = idx & 255, bf = b*8 + f;
    r1[tid] = fmaxf(g_A1g[(size_t)k*512 + tid] + g_A1t[(size_t)bf*512 + tid], 0.f);
    __syncthreads();
    {
        float s = g_A2g[(size_t)k*512 + tid] + g_A2t[(size_t)bf*512 + tid];
        for (int i = 0; i < 512; i++) s += r1[i] * g_M12[(size_t)i*512 + tid];
        r2[tid] = fmaxf(s, 0.f);
    }
    __syncthreads();
    if (tid < 256) {
        float s = g_Og[(size_t)k*256 + tid] + g_Ot[(size_t)bf*256 + tid];
        for (int i = 0; i < 512; i++)
            s += r1[i] * g_M1o[(size_t)i*256 + tid] + r2[i] * g_M2o[(size_t)i*256 + tid];
        out[b*256 + tid] = s;
    }
}

__global__ void codes_kernel(const int* __restrict__ codes, float* __restrict__ out)
{
    int t = threadIdx.x;
    float* oc = out + Bb * Dd;
    if (t < 256)      oc[t] = (float)codes[t];
    else if (t < 384) oc[t] = (float)(g_best[t - 256] & 0xffffffffu);
}

// ---------------- launch --------------------------------------------------------
extern "C" void kernel_launch(void* const* d_in, const int* in_sizes, int n_in,
                              void* d_out, int out_size)
{
    const float* x        = (const float*)d_in[0];
    const float* xhat     = (const float*)d_in[1];
    const int*   codes    = (const int*)d_in[2];
    const float* codebook = (const float*)d_in[3];
    const float* W_in     = (const float*)d_in[4];
    const float* b_in     = (const float*)d_in[5];
    const float* W_cat    = (const float*)d_in[6];
    const float* b_cat    = (const float*)d_in[7];
    const float* W1       = (const float*)d_in[8];
    const float* b1       = (const float*)d_in[9];
    const float* W2       = (const float*)d_in[10];
    const float* b2       = (const float*)d_in[11];
    const float* W_out    = (const float*)d_in[12];
    const float* b_out    = (const float*)d_in[13];
    float* out = (float*)d_out;

    float *p_h0,*p_g,*p_t,*p_A1g,*p_A2g,*p_A1t,*p_A2t,*p_Og,*p_Ot,*p_M12,*p_M1o,*p_M2o,*p_bu2,*p_bo;
    __nv_bfloat16 *p_M12b, *p_M1ob, *p_M2ob;
    cudaGetSymbolAddress((void**)&p_h0,  g_h0);
    cudaGetSymbolAddress((void**)&p_g,   g_g);
    cudaGetSymbolAddress((void**)&p_t,   g_t);
    cudaGetSymbolAddress((void**)&p_A1g, g_A1g);
    cudaGetSymbolAddress((void**)&p_A2g, g_A2g);
    cudaGetSymbolAddress((void**)&p_A1t, g_A1t);
    cudaGetSymbolAddress((void**)&p_A2t, g_A2t);
    cudaGetSymbolAddress((void**)&p_Og,  g_Og);
    cudaGetSymbolAddress((void**)&p_Ot,  g_Ot);
    cudaGetSymbolAddress((void**)&p_M12, g_M12);
    cudaGetSymbolAddress((void**)&p_M1o, g_M1o);
    cudaGetSymbolAddress((void**)&p_M2o, g_M2o);
    cudaGetSymbolAddress((void**)&p_bu2, g_bu2);
    cudaGetSymbolAddress((void**)&p_bo,  g_bo);
    cudaGetSymbolAddress((void**)&p_M12b, g_M12b);
    cudaGetSymbolAddress((void**)&p_M1ob, g_M1ob);
    cudaGetSymbolAddress((void**)&p_M2ob, g_M2ob);

    const float* W1_0 = W1;     const float* W1_1 = W1 + 256*512;
    const float* W2_0 = W2;     const float* W2_1 = W2 + 512*256;
    const float* Wc   = W_cat;  const float* Wx   = W_cat + 256*256;
    const float* b1_1 = b1 + 512;
    const float* b2_0 = b2;     const float* b2_1 = b2 + 256;

    vecmat_bias<<<2, 256>>>(p_bu2, b1_1, b2_0, nullptr, W1_1, 256, 512);
    vecmat_bias<<<1, 256>>>(p_bo,  b_out, b2_0, b2_1,   W_out, 256, 256);

    sgemm64<<<dim3(4, 4),  256>>>(codebook, W_in,  p_h0,  256, 256, 256, b_in,  nullptr);
    sgemm64<<<dim3(4, 4),  256>>>(p_h0,     Wc,    p_g,   256, 256, 256, nullptr, nullptr);
    sgemm64<<<dim3(4, 16), 256>>>(xhat,     Wx,    p_t,  1024, 256, 256, b_cat, nullptr);
    sgemm64<<<dim3(8, 4),  256>>>(p_g,      W1_0,  p_A1g, 256, 512, 256, nullptr, nullptr);
    sgemm64<<<dim3(8, 16), 256>>>(p_t,      W1_0,  p_A1t,1024, 512, 256, b1,    nullptr);
    sgemm64<<<dim3(8, 4),  256>>>(p_g,      W1_1,  p_A2g, 256, 512, 256, nullptr, nullptr);
    sgemm64<<<dim3(8, 16), 256>>>(p_t,      W1_1,  p_A2t,1024, 512, 256, p_bu2, nullptr);
    sgemm64<<<dim3(4, 4),  256>>>(p_g,      W_out, p_Og,  256, 256, 256, nullptr, codebook);
    sgemm64<<<dim3(4, 16), 256>>>(p_t,      W_out, p_Ot, 1024, 256, 256, p_bo,  xhat);
    sgemm64<<<dim3(8, 8),  256>>>(W2_0,     W1_1,  p_M12, 512, 512, 256, nullptr, nullptr);
    sgemm64<<<dim3(4, 8),  256>>>(W2_0,     W_out, p_M1o, 512, 256, 256, nullptr, nullptr);
    sgemm64<<<dim3(4, 8),  256>>>(W2_1,     W_out, p_M2o, 512, 256, 256, nullptr, nullptr);

    convT<<<1024, 256>>>(p_M12, p_M12b, 512, 512);
    convT<<<512,  256>>>(p_M1o, p_M1ob, 512, 256);
    convT<<<512,  256>>>(p_M2o, p_M2ob, 512, 256);

    initsel_kernel<<<1, 128>>>();

    cudaFuncSetAttribute(dist_mma2_kernel, cudaFuncAttributeMaxDynamicSharedMemorySize, TS_TOTAL);
    dist_mma2_kernel<<<Bb * Ff * 4, 256, TS_TOTAL>>>(x);

    selcollect_kernel<<<Bb, 256>>>();
    rescore_kernel<<<2048, 256>>>(x);
    final_kernel<<<Bb, 512>>>(out);
    codes_kernel<<<1, 384>>>(codes, out);
}